// round 17
// baseline (speedup 1.0000x reference)
#include <cuda_runtime.h>
#include <cuda_fp16.h>
#include <cstdint>
#include <stdint.h>
#include <math.h>

// ---------------- problem constants ----------------------------------------
#define BS     8
#define QLEN   2048
#define NLVL   4
#define DMODEL 256
#define LVTOT  21760    // 128^2+64^2+32^2+16^2

__device__ __constant__ int c_H[NLVL]     = {128, 64, 32, 16};
__device__ __constant__ int c_W[NLVL]     = {128, 64, 32, 16};
__device__ __constant__ int c_start[NLVL] = {0, 16384, 20480, 21504};

// ---------------- scratch (device globals) ----------------------------------
__device__ __half g_v  [(size_t)BS * LVTOT * DMODEL];   // projected values (fp16)
__device__ float  g_offattn[(size_t)BS * QLEN * 384];   // [q][0:256)=off, [256:384)=attn
__device__ __half g_acc[(size_t)BS * QLEN * DMODEL];    // sampled accumulators (fp16)
__device__ float  g_bias_oa[384];

// pre-swizzled fp16 weight images: [chunk(4)][ntile(N/128)][8192 halves]
__device__ __half g_Wvf [65536];    // W_value, N=256
__device__ __half g_Woaf[98304];    // W_off|W_attn, N=384
__device__ __half g_Wuf [65536];    // W_out, N=256

// ---------------- helpers ----------------------------------------------------
#define SWZ(o) ((o) ^ (((o) >> 3) & 0x70))

__device__ __forceinline__ uint32_t smem_u32(const void* p) {
    return (uint32_t)__cvta_generic_to_shared(p);
}

__device__ __forceinline__ void cp16(uint32_t s, const void* g) {
    asm volatile("cp.async.cg.shared.global [%0], [%1], 16;" :: "r"(s), "l"(g) : "memory");
}
__device__ __forceinline__ void cp_commit() {
    asm volatile("cp.async.commit_group;" ::: "memory");
}
__device__ __forceinline__ void cp_wait(int n) {
    if (n == 0) asm volatile("cp.async.wait_group 0;" ::: "memory");
    else        asm volatile("cp.async.wait_group 1;" ::: "memory");
}

__device__ __forceinline__ void ldsm4(uint32_t* r, uint32_t addr) {
    asm volatile("ldmatrix.sync.aligned.m8n8.x4.shared.b16 {%0,%1,%2,%3}, [%4];"
                 : "=r"(r[0]), "=r"(r[1]), "=r"(r[2]), "=r"(r[3]) : "r"(addr));
}

__device__ __forceinline__ void mma_f16(float* c, const uint32_t* a, const uint32_t* b)
{
    asm volatile(
        "mma.sync.aligned.m16n8k16.row.col.f32.f16.f16.f32 "
        "{%0,%1,%2,%3}, {%4,%5,%6,%7}, {%8,%9}, {%0,%1,%2,%3};\n"
        : "+f"(c[0]), "+f"(c[1]), "+f"(c[2]), "+f"(c[3])
        : "r"(a[0]), "r"(a[1]), "r"(a[2]), "r"(a[3]), "r"(b[0]), "r"(b[1]));
}

__device__ __forceinline__ uint32_t cvtf16(float x, float y)
{
    __half2 h = __floats2half2_rn(x, y);
    return *(uint32_t*)&h;
}

// swizzled weight-image index: block = (k/64)*(N/128) + n/128
__device__ __forceinline__ int wimg_idx(int k, int n, int N)
{
    int block = (k >> 6) * (N >> 7) + (n >> 7);
    unsigned off = SWZ((unsigned)((n & 127) * 128 + (k & 63) * 2));
    return block * 8192 + (int)(off >> 1);
}

// ---------------- single prep kernel (all weights fp16 + combined bias) -----
__global__ void prep_all(const float* __restrict__ Wv,
                         const float* __restrict__ Woff,
                         const float* __restrict__ Wattn,
                         const float* __restrict__ Wu,
                         const float* __restrict__ boff,
                         const float* __restrict__ battn)
{
    int e = blockIdx.x * 256 + threadIdx.x;
    if (e < 384) g_bias_oa[e] = (e < 256) ? boff[e] : battn[e - 256];

    if (e < 65536) {                        // W_value + W_out (both 256x256)
        int k = e >> 8, n = e & 255;
        int idx = wimg_idx(k, n, 256);
        g_Wvf[idx] = __float2half_rn(Wv[e]);
        g_Wuf[idx] = __float2half_rn(Wu[e]);
    } else if (e < 65536 + 98304) {         // W_off|W_attn fused: 256x384
        int i = e - 65536;
        int k = i / 384, n = i % 384;
        float w = (n < 256) ? Woff[k * 256 + n] : Wattn[k * 128 + (n - 256)];
        g_Woaf[wimg_idx(k, n, 384)] = __float2half_rn(w);
    }
}

// ---------------- unified fp16 GEMM body -------------------------------------
// C[128 x 64-slice] = A[128 x 256] * W + bias.  CTA 128m x 64n, 8 warps
// (warp 32m x 32n, 32 acc regs). smem 72KB: A 3-buf 16K @ (c%3)*16384;
// B 3-buf 8K @ 49152+(c%3)*8192.  ONE __syncthreads per K-chunk.
// The 64-col B slice is a contiguous 8KB half of the 16KB 128-tile image
// (SWZ permutes only within 128B rows, so the half-slice is self-consistent).
template<bool AHALF, bool CHALF>
__device__ __forceinline__ void gemm_uni(char* smem, int bx, int by,
                                         const void* Ap, const __half* __restrict__ Wf,
                                         const float* __restrict__ bias, void* Cp, int N)
{
    const int tid  = threadIdx.x;
    const int wid  = tid >> 5, lane = tid & 31;
    const int g    = lane >> 2, t = lane & 3;
    const int quad = lane >> 3, r8 = lane & 7;
    const int warp_m = wid & 3, warp_n = wid >> 2;
    const int m0 = by * 128, n0 = bx * 64;
    const int NTI = N >> 7;
    const uint32_t sbase = smem_u32(smem);

    auto issue_a = [&](int cc) {            // AHALF only: swizzled cp.async
        const char* src = (const char*)Ap + (size_t)m0 * 512 + cc * 128;
        const uint32_t d = sbase + (cc % 3) * 16384;
#pragma unroll
        for (int j = 0; j < 4; j++) {
            int idx = tid + j * 256;
            int r = idx >> 3, blk = idx & 7;
            cp16(d + SWZ((unsigned)(r * 128 + blk * 16)),
                 src + (size_t)r * 512 + blk * 16);
        }
    };
    auto issue_b = [&](int cc) {
        const char* src = (const char*)Wf + (size_t)(cc * NTI + (bx >> 1)) * 16384
                        + (bx & 1) * 8192;
        const uint32_t d = sbase + 49152 + (cc % 3) * 8192;
#pragma unroll
        for (int j = 0; j < 2; j++) {
            const int o = (tid + j * 256) * 16;
            cp16(d + o, src + o);
        }
    };

    const int a_r  = tid >> 4;
    const int a_c4 = (tid & 15) * 4;
    float4 av[8];
    auto load_a = [&](int cc) {             // fp32 path
#pragma unroll
        for (int i = 0; i < 8; i++) {
            int r = a_r + i * 16;
            av[i] = *(const float4*)((const float*)Ap + (size_t)(m0 + r) * 256 + cc * 64 + a_c4);
        }
    };
    auto store_a = [&](int cc) {
        char* bufp = smem + (cc % 3) * 16384;
#pragma unroll
        for (int i = 0; i < 8; i++) {
            int r = a_r + i * 16;
            unsigned off = SWZ((unsigned)(r * 128 + a_c4 * 2));
            *(uint2*)(bufp + off) = make_uint2(cvtf16(av[i].x, av[i].y),
                                               cvtf16(av[i].z, av[i].w));
        }
    };

    float acc[2][4][4];
#pragma unroll
    for (int i = 0; i < 2; i++)
#pragma unroll
        for (int j = 0; j < 4; j++)
#pragma unroll
            for (int r = 0; r < 4; r++) acc[i][j][r] = 0.f;

    if (AHALF) {
        issue_a(0); issue_b(0); cp_commit();
        issue_a(1); issue_b(1); cp_commit();
    } else {
        issue_b(0); cp_commit();
        issue_b(1); cp_commit();
        load_a(0); store_a(0);
    }
    cp_wait(1);
    __syncthreads();

    for (int c = 0; c < 4; c++) {
        if (!AHALF && c < 3) load_a(c + 1);

        const uint32_t sa = sbase + (c % 3) * 16384;
        const uint32_t sb = sbase + 49152 + (c % 3) * 8192;
#pragma unroll
        for (int kq = 0; kq < 4; kq++) {
            uint32_t ah[2][4];
#pragma unroll
            for (int mt = 0; mt < 2; mt++) {
                const int row = warp_m * 32 + mt * 16 + (quad & 1) * 8 + r8;
                const unsigned off = SWZ((unsigned)(row * 128 + kq * 32 + (quad >> 1) * 16));
                ldsm4(ah[mt], sa + off);
            }
#pragma unroll
            for (int nt2 = 0; nt2 < 2; nt2++) {
                const int brow = warp_n * 32 + nt2 * 16 + (quad >> 1) * 8 + r8;
                const unsigned boff = SWZ((unsigned)(brow * 128 + kq * 32 + (quad & 1) * 16));
                uint32_t bh[4];
                ldsm4(bh, sb + boff);
#pragma unroll
                for (int half = 0; half < 2; half++) {
#pragma unroll
                    for (int mt = 0; mt < 2; mt++) {
                        mma_f16(acc[mt][nt2 * 2 + half], ah[mt], bh + half * 2);
                    }
                }
            }
        }

        if (c < 3) {
            if (!AHALF) store_a(c + 1);
            if (c + 2 < 4) {
                if (AHALF) issue_a(c + 2);
                issue_b(c + 2);
                cp_commit();
            }
            cp_wait((c + 2 < 4) ? 1 : 0);
            __syncthreads();
        }
    }

#pragma unroll
    for (int mt = 0; mt < 2; mt++) {
#pragma unroll
        for (int nt = 0; nt < 4; nt++) {
            const int row = m0 + warp_m * 32 + mt * 16 + g;
            const int col = n0 + warp_n * 32 + nt * 8 + 2 * t;
            float2 bi = *(const float2*)&bias[col];
            float o0 = acc[mt][nt][0] + bi.x, o1 = acc[mt][nt][1] + bi.y;
            float o2 = acc[mt][nt][2] + bi.x, o3 = acc[mt][nt][3] + bi.y;
            if (CHALF) {
                __half* C = (__half*)Cp;
                *(__half2*)&C[(size_t)row * N + col]       = __floats2half2_rn(o0, o1);
                *(__half2*)&C[(size_t)(row + 8) * N + col] = __floats2half2_rn(o2, o3);
            } else {
                float* C = (float*)Cp;
                *(float2*)&C[(size_t)row * N + col]       = make_float2(o0, o1);
                *(float2*)&C[(size_t)(row + 8) * N + col] = make_float2(o2, o3);
            }
        }
    }
}

// ---------------- merged kernel: value proj + oa proj ------------------------
// blocks [0, 5440): value (fp32 A -> fp16 C, N=256): bx=bid&3, by=bid>>2
// blocks [5440, 6208): off/attn (fp32 A -> fp32 C, N=384): bx=t%6, by=t/6
__global__ __launch_bounds__(256, 3)
void mega_gemm(const float* __restrict__ value, const __half* __restrict__ Wvf,
               const float* __restrict__ b_value, __half* __restrict__ Cv,
               const float* __restrict__ query, const __half* __restrict__ Woaf,
               const float* __restrict__ bias_oa, float* __restrict__ Coa)
{
    extern __shared__ __align__(1024) char smem[];
    const int bid = blockIdx.x;
    if (bid < 5440) {
        gemm_uni<false, true>(smem, bid & 3, bid >> 2, value, Wvf, b_value, Cv, 256);
    } else {
        const int t2 = bid - 5440;
        gemm_uni<false, false>(smem, t2 % 6, t2 / 6, query, Woaf, bias_oa, Coa, 384);
    }
}

// ---------------- out projection: fp16 A (g_acc) via cp.async ---------------
__global__ __launch_bounds__(256, 3)
void out_gemm(const __half* __restrict__ A, const __half* __restrict__ Wuf,
              const float* __restrict__ bias, float* __restrict__ C)
{
    extern __shared__ __align__(1024) char smem[];
    const int bid = blockIdx.x;
    gemm_uni<true, false>(smem, bid & 3, bid >> 2, A, Wuf, bias, C, 256);
}

// ---------------- fused softmax + bilinear sampling (2 queries per block) ---
__global__ __launch_bounds__(256, 8)
void msda_sample2(const float* __restrict__ refer_bbox)
{
    __shared__ int   s_idx[256][4];
    __shared__ float s_w[256][4];

    const int bq0 = blockIdx.x * 2;
    const int tid = threadIdx.x;

    {
        const int task = tid >> 4;           // 0..15 = (q, h)
        const int q    = task >> 3;
        const int h    = task & 7;
        const int sub  = tid & 15;
        const int lvl  = sub >> 2;
        const int p    = sub & 3;
        const int bq   = bq0 + q;
        const int b    = bq >> 11;

        const float* qrow = g_offattn + (size_t)bq * 384;

        float logit = qrow[256 + h * 16 + sub];
        float mx = logit;
#pragma unroll
        for (int o = 8; o >= 1; o >>= 1)
            mx = fmaxf(mx, __shfl_xor_sync(0xffffffffu, mx, o));
        float e = expf(logit - mx);
        float sm = e;
#pragma unroll
        for (int o = 8; o >= 1; o >>= 1)
            sm += __shfl_xor_sync(0xffffffffu, sm, o);
        const float aw = e / sm;

        const int Hh = c_H[lvl], Ww = c_W[lvl], st = c_start[lvl];
        const float rx = refer_bbox[(size_t)bq * 8 + lvl * 2 + 0];
        const float ry = refer_bbox[(size_t)bq * 8 + lvl * 2 + 1];
        const float ox = qrow[h * 32 + lvl * 8 + p * 2 + 0];
        const float oy = qrow[h * 32 + lvl * 8 + p * 2 + 1];

        const float x = (rx + ox / (float)Ww) * (float)Ww - 0.5f;
        const float y = (ry + oy / (float)Hh) * (float)Hh - 0.5f;
        const float x0f = floorf(x), y0f = floorf(y);
        const float fx = x - x0f, fy = y - y0f;
        const int x0 = (int)x0f, y0 = (int)y0f;
        const int x1 = x0 + 1,   y1 = y0 + 1;

        const bool vx0 = (x0 >= 0) & (x0 < Ww);
        const bool vx1 = (x1 >= 0) & (x1 < Ww);
        const bool vy0 = (y0 >= 0) & (y0 < Hh);
        const bool vy1 = (y1 >= 0) & (y1 < Hh);

        float w00 = (1.f - fx) * (1.f - fy); if (!(vx0 && vy0)) w00 = 0.f;
        float w10 = fx         * (1.f - fy); if (!(vx1 && vy0)) w10 = 0.f;
        float w01 = (1.f - fx) * fy;         if (!(vx0 && vy1)) w01 = 0.f;
        float w11 = fx         * fy;         if (!(vx1 && vy1)) w11 = 0.f;

        const int cx0 = min(max(x0, 0), Ww - 1);
        const int cx1 = min(max(x1, 0), Ww - 1);
        const int cy0 = min(max(y0, 0), Hh - 1);
        const int cy1 = min(max(y1, 0), Hh - 1);

        const int base = (b * LVTOT + st) * DMODEL + h * 32;
        s_idx[tid][0] = base + (cy0 * Ww + cx0) * DMODEL;
        s_idx[tid][1] = base + (cy0 * Ww + cx1) * DMODEL;
        s_idx[tid][2] = base + (cy1 * Ww + cx0) * DMODEL;
        s_idx[tid][3] = base + (cy1 * Ww + cx1) * DMODEL;
        s_w[tid][0] = w00 * aw;
        s_w[tid][1] = w10 * aw;
        s_w[tid][2] = w01 * aw;
        s_w[tid][3] = w11 * aw;
    }
    __syncthreads();

    const int h  = tid >> 5, lane = tid & 31;
    const int pp = lane >> 4;            // point parity
    const int c2 = (lane & 15) * 2;      // channel offset (halves)
#pragma unroll
    for (int q = 0; q < 2; q++) {
        float ax = 0.f, ay = 0.f;
        const int base = q * 128 + h * 16;
#pragma unroll
        for (int j = 0; j < 16; j += 2) {
            const int4   id = *(const int4*)  s_idx[base + j + pp];
            const float4 w  = *(const float4*)s_w  [base + j + pp];
            float2 v0 = __half22float2(*(const __half2*)&g_v[id.x + c2]);
            float2 v1 = __half22float2(*(const __half2*)&g_v[id.y + c2]);
            float2 v2 = __half22float2(*(const __half2*)&g_v[id.z + c2]);
            float2 v3 = __half22float2(*(const __half2*)&g_v[id.w + c2]);
            ax = fmaf(w.x, v0.x, fmaf(w.y, v1.x, fmaf(w.z, v2.x, fmaf(w.w, v3.x, ax))));
            ay = fmaf(w.x, v0.y, fmaf(w.y, v1.y, fmaf(w.z, v2.y, fmaf(w.w, v3.y, ay))));
        }
        ax += __shfl_xor_sync(0xffffffffu, ax, 16);
        ay += __shfl_xor_sync(0xffffffffu, ay, 16);
        if (pp == 0)
            *(__half2*)&g_acc[(size_t)(bq0 + q) * DMODEL + h * 32 + c2] =
                __floats2half2_rn(ax, ay);
    }
}

// ---------------- launch -----------------------------------------------
extern "C" void kernel_launch(void* const* d_in, const int* in_sizes, int n_in,
                              void* d_out, int out_size)
{
    const float* query   = (const float*)d_in[0];
    const float* rbbox   = (const float*)d_in[1];
    const float* value   = (const float*)d_in[2];
    const float* W_value = (const float*)d_in[4];
    const float* b_value = (const float*)d_in[5];
    const float* W_off   = (const float*)d_in[6];
    const float* b_off   = (const float*)d_in[7];
    const float* W_attn  = (const float*)d_in[8];
    const float* b_attn  = (const float*)d_in[9];
    const float* W_out   = (const float*)d_in[10];
    const float* b_out   = (const float*)d_in[11];
    float* out = (float*)d_out;

    __half *pv, *pacc;
    float *poa, *pboa;
    cudaGetSymbolAddress((void**)&pv,   g_v);
    cudaGetSymbolAddress((void**)&poa,  g_offattn);
    cudaGetSymbolAddress((void**)&pacc, g_acc);
    cudaGetSymbolAddress((void**)&pboa, g_bias_oa);

    __half *wvf, *woaf, *wuf;
    cudaGetSymbolAddress((void**)&wvf,  g_Wvf);
    cudaGetSymbolAddress((void**)&woaf, g_Woaf);
    cudaGetSymbolAddress((void**)&wuf,  g_Wuf);

    static bool attr_done = false;
    if (!attr_done) {
        cudaFuncSetAttribute(mega_gemm, cudaFuncAttributeMaxDynamicSharedMemorySize, 73728);
        cudaFuncSetAttribute(out_gemm,  cudaFuncAttributeMaxDynamicSharedMemorySize, 73728);
        attr_done = true;
    }
    const int SMEM = 73728;

    // 0) all weight prep in one launch
    prep_all<<<640, 256>>>(W_value, W_off, W_attn, W_out, b_off, b_attn);

    // 1) merged: value projection (blocks 0..5439) + off/attn (5440..6207)
    mega_gemm<<<6208, 256, SMEM>>>(value, wvf, b_value, pv,
                                   query, woaf, pboa, poa);
    // 2) softmax + sampling (2 queries per block, paired-point loads)
    msda_sample2<<<BS * QLEN / 2, 256>>>(rbbox);
    // 3) output projection (fp16 A via cp.async)
    out_gemm<<<512, 256, SMEM>>>(pacc, wuf, b_out, out);
}